// round 15
// baseline (speedup 1.0000x reference)
#include <cuda_runtime.h>
#include <cuda_fp16.h>

#define N_MAX 100000
#define E_MAX 1600000

typedef unsigned long long ull;

// Scratch (allocation-free rule: __device__ globals)
__device__ __align__(16) __half2 g_AC[N_MAX * 8];      // row-role node projection, fp16 (3.2 MB)
__device__ __align__(16) __half2 g_BD[N_MAX * 8];      // col-role node projection, fp16 (3.2 MB)
__device__ __align__(16) __half2 g_Sm[2][N_MAX * 4];   // Sum of m (parity-split fp16)
__device__ __align__(16) __half2 g_S2a[2][N_MAX * 4];  // Sum of h0[row]*m
__device__ __align__(16) __half2 g_S2b[2][N_MAX * 4];  // Sum of h1[row]*m

// Software grid barrier state (zero-init; gen grows monotonically across replays)
__device__ unsigned g_bar_count;
__device__ unsigned g_bar_gen;

__device__ __forceinline__ unsigned h2_bits(__half2 h) {
    return *reinterpret_cast<unsigned*>(&h);
}
__device__ __forceinline__ __half2 bits_h2(unsigned u) {
    return *reinterpret_cast<__half2*>(&u);
}

__device__ __forceinline__ void red_add_v4_f16x2(__half2* p,
                                                 __half2 a, __half2 b,
                                                 __half2 c, __half2 d) {
    asm volatile("red.global.add.noftz.v4.f16x2 [%0], {%1, %2, %3, %4};"
                 :: "l"(p), "r"(h2_bits(a)), "r"(h2_bits(b)),
                    "r"(h2_bits(c)), "r"(h2_bits(d))
                 : "memory");
}

#define F32X2_FMA(out, a, b, c) \
    asm("fma.rn.f32x2 %0, %1, %2, %3;" : "=l"(out) : "l"(a), "l"(b), "l"(c))
#define F32X2_ADD(out, a, b) \
    asm("add.rn.f32x2 %0, %1, %2;" : "=l"(out) : "l"(a), "l"(b))
#define PACKF2(out, lo, hi) \
    asm("mov.b64 %0, {%1, %2};" : "=l"(out) : "f"(lo), "f"(hi))
#define UNPACKF2(lo, hi, in) \
    asm("mov.b64 {%0, %1}, %2;" : "=f"(lo), "=f"(hi) : "l"(in))

// Device-wide barrier. All blocks are resident (grid = 4 * numSMs enforced by
// __launch_bounds__(256, 4) + smem sizing), so spinning is deadlock-free.
__device__ __forceinline__ void grid_barrier() {
    __syncthreads();
    if (threadIdx.x == 0) {
        unsigned my_gen = *(volatile unsigned*)&g_bar_gen;  // read BEFORE arriving
        __threadfence();
        unsigned t = atomicAdd(&g_bar_count, 1);
        if (t == gridDim.x - 1) {
            g_bar_count = 0;
            __threadfence();
            atomicAdd(&g_bar_gen, 1);  // release
        } else {
            while (*(volatile unsigned*)&g_bar_gen == my_gen) {}
        }
        __threadfence();
    }
    __syncthreads();
}

// ---------------------------------------------------------------------------
// One persistent kernel: prep -> edges(k0, msg->smem) -> update1 ->
// edges(k1, msg<-smem) -> update2.
// ---------------------------------------------------------------------------
extern __shared__ uint4 smsg[];  // [EPT][256] fp16 messages, block-local

__global__ __launch_bounds__(256, 4)
void fused_kernel(const float* __restrict__ stat,
                  const float* __restrict__ dyn,
                  const int* __restrict__ eidx,
                  const float* __restrict__ ef,
                  const float* __restrict__ Wf,
                  const float* __restrict__ We1,
                  const float* __restrict__ be1,
                  const float* __restrict__ We2,
                  const float* __restrict__ be2,
                  float* __restrict__ h,
                  int N, int E, int EPT) {
    __shared__ __align__(16) float sW[32 * 16];   // We1 rows 0..31
    __shared__ __align__(16) float sWeE[64];      // We1 rows 32..35
    __shared__ __align__(16) float sbe1[16];
    __shared__ __align__(16) float sWe2[128];     // [16][8]
    __shared__ __align__(16) float sbe2[8];
    __shared__ __align__(16) float sWf[192];      // W_filter[0..2], 8x8 each

    int tid = threadIdx.x;
    for (int i = tid; i < 512; i += 256) sW[i] = We1[i];
    for (int i = tid; i < 64; i += 256) sWeE[i] = We1[512 + i];
    for (int i = tid; i < 16; i += 256) sbe1[i] = be1[i];
    for (int i = tid; i < 128; i += 256) sWe2[i] = We2[i];
    for (int i = tid; i < 8; i += 256) sbe2[i] = be2[i];
    for (int i = tid; i < 192; i += 256) sWf[i] = Wf[i];
    __syncthreads();

    int T = gridDim.x * 256;
    int gtid = blockIdx.x * 256 + tid;

    // ---------------- Phase 0: per-node prep ----------------
    for (int n = gtid; n < N; n += T) {
        float s[8], d[8];
        {
            const float4* sp = (const float4*)stat + n * 2;
            float4 t0 = sp[0], t1 = sp[1];
            s[0] = t0.x; s[1] = t0.y; s[2] = t0.z; s[3] = t0.w;
            s[4] = t1.x; s[5] = t1.y; s[6] = t1.z; s[7] = t1.w;
            const float4* dp = (const float4*)dyn + n * 2;
            float4 u0 = dp[0], u1 = dp[1];
            d[0] = u0.x; d[1] = u0.y; d[2] = u0.z; d[3] = u0.w;
            d[4] = u1.x; d[5] = u1.y; d[6] = u1.z; d[7] = u1.w;
        }
        float ac[16], bd[16];
#pragma unroll
        for (int j = 0; j < 16; j++) { ac[j] = 0.f; bd[j] = 0.f; }
#pragma unroll
        for (int i = 0; i < 8; i++) {
            float si = s[i], di = d[i];
#pragma unroll
            for (int j = 0; j < 16; j++) {
                ac[j] += si * sW[i * 16 + j];
                ac[j] += di * sW[(16 + i) * 16 + j];
                bd[j] += si * sW[(8 + i) * 16 + j];
                bd[j] += di * sW[(24 + i) * 16 + j];
            }
        }
        {
            uint4* acp = (uint4*)(g_AC + n * 8);
            uint4* bdp = (uint4*)(g_BD + n * 8);
            __half2 a[8], b[8];
#pragma unroll
            for (int q = 0; q < 8; q++) {
                a[q] = __floats2half2_rn(ac[q * 2], ac[q * 2 + 1]);
                b[q] = __floats2half2_rn(bd[q * 2], bd[q * 2 + 1]);
            }
            acp[0] = make_uint4(h2_bits(a[0]), h2_bits(a[1]), h2_bits(a[2]), h2_bits(a[3]));
            acp[1] = make_uint4(h2_bits(a[4]), h2_bits(a[5]), h2_bits(a[6]), h2_bits(a[7]));
            bdp[0] = make_uint4(h2_bits(b[0]), h2_bits(b[1]), h2_bits(b[2]), h2_bits(b[3]));
            bdp[1] = make_uint4(h2_bits(b[4]), h2_bits(b[5]), h2_bits(b[6]), h2_bits(b[7]));
        }
        float h0[8];
#pragma unroll
        for (int j = 0; j < 8; j++) h0[j] = 0.f;
#pragma unroll
        for (int i = 0; i < 8; i++) {
            float di = d[i];
#pragma unroll
            for (int j = 0; j < 8; j++) h0[j] += di * sWf[i * 8 + j];
        }
        float4* hp = (float4*)h + n * 2;
        hp[0] = make_float4(h0[0], h0[1], h0[2], h0[3]);
        hp[1] = make_float4(h0[4], h0[5], h0[6], h0[7]);

        uint4 z = make_uint4(0u, 0u, 0u, 0u);
        ((uint4*)(g_Sm[0]  + n * 4))[0] = z;
        ((uint4*)(g_Sm[1]  + n * 4))[0] = z;
        ((uint4*)(g_S2a[0] + n * 4))[0] = z;
        ((uint4*)(g_S2a[1] + n * 4))[0] = z;
        ((uint4*)(g_S2b[0] + n * 4))[0] = z;
        ((uint4*)(g_S2b[1] + n * 4))[0] = z;
    }

    grid_barrier();

    // ---------------- Phase 1: edges k=0 (msg -> smem) ----------------
    for (int it = 0; it < EPT; it++) {
        int e = gtid + it * T;
        if (e >= E) break;
        int row = eidx[e];
        int col = eidx[E + e];
        int p = e & 1;

        const uint4* acp = (const uint4*)(g_AC + row * 8);
        const uint4* bdp = (const uint4*)(g_BD + col * 8);
        uint4 pa0 = acp[0], pa1 = acp[1];
        uint4 pb0 = bdp[0], pb1 = bdp[1];
        const float4* hr = (const float4*)h + row * 2;
        float4 r0 = hr[0], r1 = hr[1];
        float4 efv = ((const float4*)ef)[e];

        ull hid2[8];
        {
            unsigned aw[8] = {pa0.x, pa0.y, pa0.z, pa0.w, pa1.x, pa1.y, pa1.z, pa1.w};
            unsigned bw[8] = {pb0.x, pb0.y, pb0.z, pb0.w, pb1.x, pb1.y, pb1.z, pb1.w};
#pragma unroll
            for (int q = 0; q < 8; q++) {
                __half2 hs = __hadd2(bits_h2(aw[q]), bits_h2(bw[q]));
                float2 f = __half22float2(hs);
                ull t; PACKF2(t, f.x, f.y);
                F32X2_ADD(hid2[q], t, *(const ull*)&sbe1[2 * q]);
            }
        }
        {
            ull e0, e1, e2, e3;
            PACKF2(e0, efv.x, efv.x);
            PACKF2(e1, efv.y, efv.y);
            PACKF2(e2, efv.z, efv.z);
            PACKF2(e3, efv.w, efv.w);
#pragma unroll
            for (int q = 0; q < 8; q++) {
                F32X2_FMA(hid2[q], e0, *(const ull*)&sWeE[2 * q],      hid2[q]);
                F32X2_FMA(hid2[q], e1, *(const ull*)&sWeE[16 + 2 * q], hid2[q]);
                F32X2_FMA(hid2[q], e2, *(const ull*)&sWeE[32 + 2 * q], hid2[q]);
                F32X2_FMA(hid2[q], e3, *(const ull*)&sWeE[48 + 2 * q], hid2[q]);
            }
        }
        float hv[16];
#pragma unroll
        for (int q = 0; q < 8; q++) {
            float lo, hi;
            UNPACKF2(lo, hi, hid2[q]);
            hv[2 * q + 0] = fmaxf(lo, 0.f);
            hv[2 * q + 1] = fmaxf(hi, 0.f);
        }
        ull acc[4];
#pragma unroll
        for (int q = 0; q < 4; q++) acc[q] = *(const ull*)&sbe2[2 * q];
#pragma unroll
        for (int j = 0; j < 16; j++) {
            ull hjj; PACKF2(hjj, hv[j], hv[j]);
#pragma unroll
            for (int q = 0; q < 4; q++)
                F32X2_FMA(acc[q], hjj, *(const ull*)&sWe2[j * 8 + 2 * q], acc[q]);
        }
        float m[8];
#pragma unroll
        for (int q = 0; q < 4; q++) UNPACKF2(m[2 * q], m[2 * q + 1], acc[q]);

        float ss = 0.f;
#pragma unroll
        for (int d = 0; d < 8; d++) ss += m[d] * m[d];
        float inv = (ss > 0.f) ? rsqrtf(ss) : 0.f;
#pragma unroll
        for (int d = 0; d < 8; d++) m[d] *= inv;

        __half2 p0 = __floats2half2_rn(m[0], m[1]);
        __half2 p1 = __floats2half2_rn(m[2], m[3]);
        __half2 p2 = __floats2half2_rn(m[4], m[5]);
        __half2 p3 = __floats2half2_rn(m[6], m[7]);
        smsg[it * 256 + tid] = make_uint4(h2_bits(p0), h2_bits(p1), h2_bits(p2), h2_bits(p3));

        red_add_v4_f16x2(g_Sm[p] + col * 4, p0, p1, p2, p3);

        __half2 s0 = __floats2half2_rn(r0.x * m[0], r0.y * m[1]);
        __half2 s1 = __floats2half2_rn(r0.z * m[2], r0.w * m[3]);
        __half2 s2 = __floats2half2_rn(r1.x * m[4], r1.y * m[5]);
        __half2 s3 = __floats2half2_rn(r1.z * m[6], r1.w * m[7]);
        red_add_v4_f16x2(g_S2a[p] + col * 4, s0, s1, s2, s3);
    }

    grid_barrier();

    // ---------------- Phase 2: update h1 ----------------
    for (int n = gtid; n < N; n += T) {
        uint4 sm0 = ((const uint4*)(g_Sm[0] + n * 4))[0];
        uint4 sm1 = ((const uint4*)(g_Sm[1] + n * 4))[0];
        uint4 sa0 = ((const uint4*)(g_S2a[0] + n * 4))[0];
        uint4 sa1 = ((const uint4*)(g_S2a[1] + n * 4))[0];
        float sm[8], s2[8];
        {
            const unsigned* w0 = &sm0.x; const unsigned* w1 = &sm1.x;
            const unsigned* v0 = &sa0.x; const unsigned* v1 = &sa1.x;
#pragma unroll
            for (int q = 0; q < 4; q++) {
                float2 fa0 = __half22float2(bits_h2(w0[q]));
                float2 fa1 = __half22float2(bits_h2(w1[q]));
                float2 fb0 = __half22float2(bits_h2(v0[q]));
                float2 fb1 = __half22float2(bits_h2(v1[q]));
                sm[q * 2 + 0] = fa0.x + fa1.x;
                sm[q * 2 + 1] = fa0.y + fa1.y;
                s2[q * 2 + 0] = fb0.x + fb1.x;
                s2[q * 2 + 1] = fb0.y + fb1.y;
            }
        }
        float4* hp = (float4*)h + n * 2;
        float4 h0 = hp[0], h1 = hp[1];
        float hv[8] = {h0.x, h0.y, h0.z, h0.w, h1.x, h1.y, h1.z, h1.w};
        float a[8];
#pragma unroll
        for (int j = 0; j < 8; j++) a[j] = hv[j] * sm[j] - s2[j];
        float o[8] = {hv[0], hv[1], hv[2], hv[3], hv[4], hv[5], hv[6], hv[7]};
#pragma unroll
        for (int i = 0; i < 8; i++) {
            float ai = a[i];
#pragma unroll
            for (int j = 0; j < 8; j++) o[j] += ai * sWf[64 + i * 8 + j];
        }
        hp[0] = make_float4(o[0], o[1], o[2], o[3]);
        hp[1] = make_float4(o[4], o[5], o[6], o[7]);
    }

    grid_barrier();

    // ---------------- Phase 3: edges k=1 (msg <- smem) ----------------
    for (int it = 0; it < EPT; it++) {
        int e = gtid + it * T;
        if (e >= E) break;
        int row = eidx[e];
        int col = eidx[E + e];

        uint4 pk = smsg[it * 256 + tid];
        const float4* hr = (const float4*)h + row * 2;
        float4 r0 = hr[0], r1 = hr[1];

        float2 m0 = __half22float2(bits_h2(pk.x));
        float2 m1 = __half22float2(bits_h2(pk.y));
        float2 m2 = __half22float2(bits_h2(pk.z));
        float2 m3 = __half22float2(bits_h2(pk.w));

        __half2 s0 = __floats2half2_rn(r0.x * m0.x, r0.y * m0.y);
        __half2 s1 = __floats2half2_rn(r0.z * m1.x, r0.w * m1.y);
        __half2 s2 = __floats2half2_rn(r1.x * m2.x, r1.y * m2.y);
        __half2 s3 = __floats2half2_rn(r1.z * m3.x, r1.w * m3.y);
        red_add_v4_f16x2(g_S2b[e & 1] + col * 4, s0, s1, s2, s3);
    }

    grid_barrier();

    // ---------------- Phase 4: update h2 ----------------
    for (int n = gtid; n < N; n += T) {
        uint4 sm0 = ((const uint4*)(g_Sm[0] + n * 4))[0];
        uint4 sm1 = ((const uint4*)(g_Sm[1] + n * 4))[0];
        uint4 sa0 = ((const uint4*)(g_S2b[0] + n * 4))[0];
        uint4 sa1 = ((const uint4*)(g_S2b[1] + n * 4))[0];
        float sm[8], s2[8];
        {
            const unsigned* w0 = &sm0.x; const unsigned* w1 = &sm1.x;
            const unsigned* v0 = &sa0.x; const unsigned* v1 = &sa1.x;
#pragma unroll
            for (int q = 0; q < 4; q++) {
                float2 fa0 = __half22float2(bits_h2(w0[q]));
                float2 fa1 = __half22float2(bits_h2(w1[q]));
                float2 fb0 = __half22float2(bits_h2(v0[q]));
                float2 fb1 = __half22float2(bits_h2(v1[q]));
                sm[q * 2 + 0] = fa0.x + fa1.x;
                sm[q * 2 + 1] = fa0.y + fa1.y;
                s2[q * 2 + 0] = fb0.x + fb1.x;
                s2[q * 2 + 1] = fb0.y + fb1.y;
            }
        }
        float4* hp = (float4*)h + n * 2;
        float4 h0 = hp[0], h1 = hp[1];
        float hv[8] = {h0.x, h0.y, h0.z, h0.w, h1.x, h1.y, h1.z, h1.w};
        float a[8];
#pragma unroll
        for (int j = 0; j < 8; j++) a[j] = hv[j] * sm[j] - s2[j];
        float o[8] = {hv[0], hv[1], hv[2], hv[3], hv[4], hv[5], hv[6], hv[7]};
#pragma unroll
        for (int i = 0; i < 8; i++) {
            float ai = a[i];
#pragma unroll
            for (int j = 0; j < 8; j++) o[j] += ai * sWf[128 + i * 8 + j];
        }
        hp[0] = make_float4(o[0], o[1], o[2], o[3]);
        hp[1] = make_float4(o[4], o[5], o[6], o[7]);
    }
}

// ---------------------------------------------------------------------------
extern "C" void kernel_launch(void* const* d_in, const int* in_sizes, int n_in,
                              void* d_out, int out_size) {
    const float* stat = (const float*)d_in[0];
    const float* dyn  = (const float*)d_in[1];
    const int*   eidx = (const int*)d_in[2];
    const float* ef   = (const float*)d_in[3];
    const float* Wf   = (const float*)d_in[4];
    const float* We1  = (const float*)d_in[5];
    const float* be1  = (const float*)d_in[6];
    const float* We2  = (const float*)d_in[7];
    const float* be2  = (const float*)d_in[8];
    float* h = (float*)d_out;

    int N = in_sizes[1] / 8;
    int E = in_sizes[2] / 2;
    if (N > N_MAX) N = N_MAX;
    if (E > E_MAX) E = E_MAX;

    int dev = 0, sms = 148;
    cudaGetDevice(&dev);
    cudaDeviceGetAttribute(&sms, cudaDevAttrMultiProcessorCount, dev);

    int blocks = sms * 4;                 // matches __launch_bounds__(256, 4)
    int T = blocks * 256;
    int EPT = (E + T - 1) / T;
    size_t smem = (size_t)EPT * 256 * sizeof(uint4);

    // Allow >48KB dynamic smem if EPT lands at 12+ (smaller SM counts).
    cudaFuncSetAttribute(fused_kernel, cudaFuncAttributeMaxDynamicSharedMemorySize,
                         (int)smem > 48 * 1024 ? (int)smem : 48 * 1024);

    fused_kernel<<<blocks, 256, smem>>>(stat, dyn, eidx, ef, Wf, We1, be1, We2, be2,
                                        h, N, E, EPT);
}

// round 17
// speedup vs baseline: 1.8841x; 1.8841x over previous
#include <cuda_runtime.h>
#include <cuda_fp16.h>

// Problem constants (shapes fixed by the reference)
#define N_MAX 100000
#define E_MAX 1600000

typedef unsigned long long ull;

// Scratch (allocation-free rule: __device__ globals)
__device__ __align__(16) __half2 g_msg[E_MAX * 4];     // normalized edge messages, fp16 (25.6 MB)
__device__ __align__(16) __half2 g_AC[N_MAX * 8];      // row-role node projection, fp16 (3.2 MB)
__device__ __align__(16) __half2 g_BD[N_MAX * 8];      // col-role node projection, fp16 (3.2 MB)
// Parity-split fp16 accumulators (reduce fp16 running-sum rounding ~sqrt(2)).
__device__ __align__(16) __half2 g_Sm[2][N_MAX * 4];   // Sum of m over incoming edges
__device__ __align__(16) __half2 g_S2a[2][N_MAX * 4];  // Sum of h0[row]*m  (k = 0)
__device__ __align__(16) __half2 g_S2b[2][N_MAX * 4];  // Sum of h1[row]*m  (k = 1)

__device__ __forceinline__ unsigned h2_bits(__half2 h) {
    return *reinterpret_cast<unsigned*>(&h);
}
__device__ __forceinline__ __half2 bits_h2(unsigned u) {
    return *reinterpret_cast<__half2*>(&u);
}

// One 16B vector reduction carrying 8 fp16 accumulators (sm_90+).
__device__ __forceinline__ void red_add_v4_f16x2(__half2* p,
                                                 __half2 a, __half2 b,
                                                 __half2 c, __half2 d) {
    asm volatile("red.global.add.noftz.v4.f16x2 [%0], {%1, %2, %3, %4};"
                 :: "l"(p), "r"(h2_bits(a)), "r"(h2_bits(b)),
                    "r"(h2_bits(c)), "r"(h2_bits(d))
                 : "memory");
}

// Packed f32x2 ops (Blackwell sm_100+, PTX ISA 8.6) — 2 fp32 lanes per instr.
#define F32X2_FMA(out, a, b, c) \
    asm("fma.rn.f32x2 %0, %1, %2, %3;" : "=l"(out) : "l"(a), "l"(b), "l"(c))
#define F32X2_ADD(out, a, b) \
    asm("add.rn.f32x2 %0, %1, %2;" : "=l"(out) : "l"(a), "l"(b))
#define PACKF2(out, lo, hi) \
    asm("mov.b64 %0, {%1, %2};" : "=l"(out) : "f"(lo), "f"(hi))
#define UNPACKF2(lo, hi, in) \
    asm("mov.b64 {%0, %1}, %2;" : "=f"(lo), "=f"(hi) : "l"(in))

// ---------------------------------------------------------------------------
// Kernel 1: per-node prep.
// ---------------------------------------------------------------------------
__global__ void prep_kernel(const float* __restrict__ stat,
                            const float* __restrict__ dyn,
                            const float* __restrict__ We1,
                            const float* __restrict__ Wf0,
                            float* __restrict__ h, int N) {
    __shared__ float sW[32 * 16 + 64];  // We1 rows 0..31, then W_filter[0] (8x8)
    for (int i = threadIdx.x; i < 32 * 16; i += blockDim.x) sW[i] = We1[i];
    for (int i = threadIdx.x; i < 64; i += blockDim.x) sW[512 + i] = Wf0[i];
    __syncthreads();

    int n = blockIdx.x * blockDim.x + threadIdx.x;
    if (n >= N) return;

    float s[8], d[8];
    {
        const float4* sp = (const float4*)stat + n * 2;
        float4 t0 = sp[0], t1 = sp[1];
        s[0] = t0.x; s[1] = t0.y; s[2] = t0.z; s[3] = t0.w;
        s[4] = t1.x; s[5] = t1.y; s[6] = t1.z; s[7] = t1.w;
        const float4* dp = (const float4*)dyn + n * 2;
        float4 u0 = dp[0], u1 = dp[1];
        d[0] = u0.x; d[1] = u0.y; d[2] = u0.z; d[3] = u0.w;
        d[4] = u1.x; d[5] = u1.y; d[6] = u1.z; d[7] = u1.w;
    }

    float ac[16], bd[16];
#pragma unroll
    for (int j = 0; j < 16; j++) { ac[j] = 0.f; bd[j] = 0.f; }
#pragma unroll
    for (int i = 0; i < 8; i++) {
        float si = s[i], di = d[i];
#pragma unroll
        for (int j = 0; j < 16; j++) {
            ac[j] += si * sW[i * 16 + j];
            ac[j] += di * sW[(16 + i) * 16 + j];
            bd[j] += si * sW[(8 + i) * 16 + j];
            bd[j] += di * sW[(24 + i) * 16 + j];
        }
    }

    // pack to fp16: 16 halfs = 2 x 16B stores per array
    {
        uint4* acp = (uint4*)(g_AC + n * 8);
        uint4* bdp = (uint4*)(g_BD + n * 8);
        __half2 a[8], b[8];
#pragma unroll
        for (int q = 0; q < 8; q++) {
            a[q] = __floats2half2_rn(ac[q * 2], ac[q * 2 + 1]);
            b[q] = __floats2half2_rn(bd[q * 2], bd[q * 2 + 1]);
        }
        acp[0] = make_uint4(h2_bits(a[0]), h2_bits(a[1]), h2_bits(a[2]), h2_bits(a[3]));
        acp[1] = make_uint4(h2_bits(a[4]), h2_bits(a[5]), h2_bits(a[6]), h2_bits(a[7]));
        bdp[0] = make_uint4(h2_bits(b[0]), h2_bits(b[1]), h2_bits(b[2]), h2_bits(b[3]));
        bdp[1] = make_uint4(h2_bits(b[4]), h2_bits(b[5]), h2_bits(b[6]), h2_bits(b[7]));
    }

    // h0 = dyn @ W_filter[0]
    float h0[8];
#pragma unroll
    for (int j = 0; j < 8; j++) h0[j] = 0.f;
#pragma unroll
    for (int i = 0; i < 8; i++) {
        float di = d[i];
#pragma unroll
        for (int j = 0; j < 8; j++) h0[j] += di * sW[512 + i * 8 + j];
    }
    float4* hp = (float4*)h + n * 2;
    hp[0] = make_float4(h0[0], h0[1], h0[2], h0[3]);
    hp[1] = make_float4(h0[4], h0[5], h0[6], h0[7]);

    uint4 z = make_uint4(0u, 0u, 0u, 0u);
    ((uint4*)(g_Sm[0]  + n * 4))[0] = z;
    ((uint4*)(g_Sm[1]  + n * 4))[0] = z;
    ((uint4*)(g_S2a[0] + n * 4))[0] = z;
    ((uint4*)(g_S2a[1] + n * 4))[0] = z;
    ((uint4*)(g_S2b[0] + n * 4))[0] = z;
    ((uint4*)(g_S2b[1] + n * 4))[0] = z;
}

// ---------------------------------------------------------------------------
// Kernel 2: per-edge — MLP (packed f32x2), normalize, store msg (fp16),
// accumulate Sm[col] += m and S2a[col] += h0[row]*m.
// __launch_bounds__(256, 5): cap regs ~51 to lift occupancy from ~50% to
// ~62% — the session-wide pattern says edge-kernel time tracks occupancy.
// ---------------------------------------------------------------------------
__global__ __launch_bounds__(256, 5)
void edge0_kernel(const int* __restrict__ eidx,
                  const float* __restrict__ ef,
                  const float* __restrict__ We1,
                  const float* __restrict__ be1,
                  const float* __restrict__ We2,
                  const float* __restrict__ be2,
                  const float* __restrict__ h, int E) {
    __shared__ __align__(16) float sWeE[64];   // We1 rows 32..35 ([4][16])
    __shared__ __align__(16) float sbe1[16];
    __shared__ __align__(16) float sWe2[128];  // [16][8]
    __shared__ __align__(16) float sbe2[8];
    for (int i = threadIdx.x; i < 64; i += blockDim.x) sWeE[i] = We1[512 + i];
    for (int i = threadIdx.x; i < 16; i += blockDim.x) sbe1[i] = be1[i];
    for (int i = threadIdx.x; i < 128; i += blockDim.x) sWe2[i] = We2[i];
    for (int i = threadIdx.x; i < 8; i += blockDim.x) sbe2[i] = be2[i];
    __syncthreads();

    int e = blockIdx.x * blockDim.x + threadIdx.x;
    if (e >= E) return;

    int row = eidx[e];
    int col = eidx[E + e];
    int p = e & 1;

    // front-batch the gathers: AC[row] (32B), BD[col] (32B), h0[row], ef
    const uint4* acp = (const uint4*)(g_AC + row * 8);
    const uint4* bdp = (const uint4*)(g_BD + col * 8);
    uint4 pa0 = acp[0], pa1 = acp[1];
    uint4 pb0 = bdp[0], pb1 = bdp[1];
    const float4* hr = (const float4*)h + row * 2;
    float4 r0 = hr[0], r1 = hr[1];
    float4 efv = ((const float4*)ef)[e];

    // hid2[q] = f32x2 pair (2q, 2q+1) of: AC[row] + BD[col] + be1
    ull hid2[8];
    {
        unsigned aw[8] = {pa0.x, pa0.y, pa0.z, pa0.w, pa1.x, pa1.y, pa1.z, pa1.w};
        unsigned bw[8] = {pb0.x, pb0.y, pb0.z, pb0.w, pb1.x, pb1.y, pb1.z, pb1.w};
#pragma unroll
        for (int q = 0; q < 8; q++) {
            __half2 hs = __hadd2(bits_h2(aw[q]), bits_h2(bw[q]));
            float2 f = __half22float2(hs);
            ull t; PACKF2(t, f.x, f.y);
            F32X2_ADD(hid2[q], t, *(const ull*)&sbe1[2 * q]);
        }
    }

    // hid2 += ef @ We1[32:36]  (pairs along j; 32 packed FMAs)
    {
        ull e0, e1, e2, e3;
        PACKF2(e0, efv.x, efv.x);
        PACKF2(e1, efv.y, efv.y);
        PACKF2(e2, efv.z, efv.z);
        PACKF2(e3, efv.w, efv.w);
#pragma unroll
        for (int q = 0; q < 8; q++) {
            F32X2_FMA(hid2[q], e0, *(const ull*)&sWeE[2 * q],      hid2[q]);
            F32X2_FMA(hid2[q], e1, *(const ull*)&sWeE[16 + 2 * q], hid2[q]);
            F32X2_FMA(hid2[q], e2, *(const ull*)&sWeE[32 + 2 * q], hid2[q]);
            F32X2_FMA(hid2[q], e3, *(const ull*)&sWeE[48 + 2 * q], hid2[q]);
        }
    }

    // ReLU (scalar), then m = hidden @ We2 + be2 with d-pairs packed (64 FMAs)
    float hv[16];
#pragma unroll
    for (int q = 0; q < 8; q++) {
        float lo, hi;
        UNPACKF2(lo, hi, hid2[q]);
        hv[2 * q + 0] = fmaxf(lo, 0.f);
        hv[2 * q + 1] = fmaxf(hi, 0.f);
    }
    ull acc[4];
#pragma unroll
    for (int q = 0; q < 4; q++) acc[q] = *(const ull*)&sbe2[2 * q];
#pragma unroll
    for (int j = 0; j < 16; j++) {
        ull hjj; PACKF2(hjj, hv[j], hv[j]);
#pragma unroll
        for (int q = 0; q < 4; q++)
            F32X2_FMA(acc[q], hjj, *(const ull*)&sWe2[j * 8 + 2 * q], acc[q]);
    }
    float m[8];
#pragma unroll
    for (int q = 0; q < 4; q++) UNPACKF2(m[2 * q], m[2 * q + 1], acc[q]);

    // normalize (0 when norm == 0)
    float ss = 0.f;
#pragma unroll
    for (int d = 0; d < 8; d++) ss += m[d] * m[d];
    float inv = (ss > 0.f) ? rsqrtf(ss) : 0.f;
#pragma unroll
    for (int d = 0; d < 8; d++) m[d] *= inv;

    // pack msg to fp16; store once, reuse the packs for the Sm reduction
    __half2 p0 = __floats2half2_rn(m[0], m[1]);
    __half2 p1 = __floats2half2_rn(m[2], m[3]);
    __half2 p2 = __floats2half2_rn(m[4], m[5]);
    __half2 p3 = __floats2half2_rn(m[6], m[7]);
    ((uint4*)(g_msg + e * 4))[0] =
        make_uint4(h2_bits(p0), h2_bits(p1), h2_bits(p2), h2_bits(p3));

    // Sm[col] += m
    red_add_v4_f16x2(g_Sm[p] + col * 4, p0, p1, p2, p3);

    // S2a[col] += h0[row] * m
    __half2 s0 = __floats2half2_rn(r0.x * m[0], r0.y * m[1]);
    __half2 s1 = __floats2half2_rn(r0.z * m[2], r0.w * m[3]);
    __half2 s2 = __floats2half2_rn(r1.x * m[4], r1.y * m[5]);
    __half2 s3 = __floats2half2_rn(r1.z * m[6], r1.w * m[7]);
    red_add_v4_f16x2(g_S2a[p] + col * 4, s0, s1, s2, s3);
}

// ---------------------------------------------------------------------------
// Kernel 3: per-edge pass for k = 1:  S2b[col] += h1[row] * m.
// (1 edge/thread, 82% occ — empirically optimal; do not touch.)
// ---------------------------------------------------------------------------
__global__ void flux_kernel(const int* __restrict__ eidx,
                            const float* __restrict__ h, int E) {
    int e = blockIdx.x * blockDim.x + threadIdx.x;
    if (e >= E) return;

    int row = eidx[e];
    int col = eidx[E + e];
    int p = e & 1;

    uint4 pk = ((const uint4*)(g_msg + e * 4))[0];
    const float4* hr = (const float4*)h + row * 2;
    float4 r0 = hr[0], r1 = hr[1];

    float2 m0 = __half22float2(bits_h2(pk.x));
    float2 m1 = __half22float2(bits_h2(pk.y));
    float2 m2 = __half22float2(bits_h2(pk.z));
    float2 m3 = __half22float2(bits_h2(pk.w));

    __half2 s0 = __floats2half2_rn(r0.x * m0.x, r0.y * m0.y);
    __half2 s1 = __floats2half2_rn(r0.z * m1.x, r0.w * m1.y);
    __half2 s2 = __floats2half2_rn(r1.x * m2.x, r1.y * m2.y);
    __half2 s3 = __floats2half2_rn(r1.z * m3.x, r1.w * m3.y);
    red_add_v4_f16x2(g_S2b[p] + col * 4, s0, s1, s2, s3);
}

// ---------------------------------------------------------------------------
// Kernel 4: agg[n] = h[n]*Sm[n] - S2[n];  h += agg @ W_filter[k+1].
// which_s2: 0 -> S2a (k=0), 1 -> S2b (k=1).
// ---------------------------------------------------------------------------
__global__ void update_kernel(const float* __restrict__ Wk,
                              float* __restrict__ h, int N, int which_s2) {
    __shared__ float sW[64];
    if (threadIdx.x < 64) sW[threadIdx.x] = Wk[threadIdx.x];
    __syncthreads();

    int n = blockIdx.x * blockDim.x + threadIdx.x;
    if (n >= N) return;

    const __half2* s2base0 = which_s2 ? g_S2b[0] : g_S2a[0];
    const __half2* s2base1 = which_s2 ? g_S2b[1] : g_S2a[1];

    uint4 sm0 = ((const uint4*)(g_Sm[0] + n * 4))[0];
    uint4 sm1 = ((const uint4*)(g_Sm[1] + n * 4))[0];
    uint4 sa0 = ((const uint4*)(s2base0 + n * 4))[0];
    uint4 sa1 = ((const uint4*)(s2base1 + n * 4))[0];

    float sm[8], s2[8];
    {
        const unsigned* w0 = &sm0.x;
        const unsigned* w1 = &sm1.x;
        const unsigned* v0 = &sa0.x;
        const unsigned* v1 = &sa1.x;
#pragma unroll
        for (int q = 0; q < 4; q++) {
            float2 fa0 = __half22float2(bits_h2(w0[q]));
            float2 fa1 = __half22float2(bits_h2(w1[q]));
            float2 fb0 = __half22float2(bits_h2(v0[q]));
            float2 fb1 = __half22float2(bits_h2(v1[q]));
            sm[q * 2 + 0] = fa0.x + fa1.x;
            sm[q * 2 + 1] = fa0.y + fa1.y;
            s2[q * 2 + 0] = fb0.x + fb1.x;
            s2[q * 2 + 1] = fb0.y + fb1.y;
        }
    }

    float4* hp = (float4*)h + n * 2;
    float4 h0 = hp[0], h1 = hp[1];
    float hv[8] = {h0.x, h0.y, h0.z, h0.w, h1.x, h1.y, h1.z, h1.w};

    float a[8];
#pragma unroll
    for (int j = 0; j < 8; j++) a[j] = hv[j] * sm[j] - s2[j];

    float o[8] = {hv[0], hv[1], hv[2], hv[3], hv[4], hv[5], hv[6], hv[7]};
#pragma unroll
    for (int i = 0; i < 8; i++) {
        float ai = a[i];
#pragma unroll
        for (int j = 0; j < 8; j++) o[j] += ai * sW[i * 8 + j];
    }
    hp[0] = make_float4(o[0], o[1], o[2], o[3]);
    hp[1] = make_float4(o[4], o[5], o[6], o[7]);
}

// ---------------------------------------------------------------------------
extern "C" void kernel_launch(void* const* d_in, const int* in_sizes, int n_in,
                              void* d_out, int out_size) {
    const float* stat = (const float*)d_in[0];   // [N, 8]
    const float* dyn  = (const float*)d_in[1];   // [N, 8]
    const int*   eidx = (const int*)d_in[2];     // [2, E]
    const float* ef   = (const float*)d_in[3];   // [E, 4]
    const float* Wf   = (const float*)d_in[4];   // [3, 8, 8]
    const float* We1  = (const float*)d_in[5];   // [36, 16]
    const float* be1  = (const float*)d_in[6];   // [16]
    const float* We2  = (const float*)d_in[7];   // [16, 8]
    const float* be2  = (const float*)d_in[8];   // [8]

    float* h = (float*)d_out;                    // [N, 8] — used as live h buffer

    int N = in_sizes[1] / 8;
    int E = in_sizes[2] / 2;
    if (N > N_MAX) N = N_MAX;
    if (E > E_MAX) E = E_MAX;

    int nb = (N + 255) / 256;
    int eb = (E + 255) / 256;

    prep_kernel<<<nb, 256>>>(stat, dyn, We1, Wf, h, N);
    edge0_kernel<<<eb, 256>>>(eidx, ef, We1, be1, We2, be2, h, E);
    update_kernel<<<nb, 256>>>(Wf + 64, h, N, 0);   // h1 = h0 + (h0*Sm - S2a)@W1
    flux_kernel<<<eb, 256>>>(eidx, h, E);
    update_kernel<<<nb, 256>>>(Wf + 128, h, N, 1);  // h2 = h1 + (h1*Sm - S2b)@W2
}